// round 1
// baseline (speedup 1.0000x reference)
#include <cuda_runtime.h>
#include <math.h>

#define N_ENT 4096
#define BATCH 4
#define NHID  3
#define NT    512
#define NJ    8          // j columns per thread (512*8 = 4096)
#define NR    4          // rows per tile
#define NTILES (BATCH*(N_ENT/NR))   // 4096

// ---------------- device scratch (no allocations allowed) ----------------
__device__ float4 g_tabA[N_ENT];        // p, q, dst, h0
__device__ float2 g_tabB[N_ENT];        // h1, h2
__device__ float  g_src[N_ENT];
__device__ float4 g_rowc[N_ENT];        // u, v, w0, thr(=-src)
__device__ float  g_dstmax;
__device__ float  g_acc[BATCH*N_ENT*4]; // denom, num0, num1, num2
__device__ float  g_x[BATCH*N_ENT*NHID];

// ---------------- K1: h = emb@W, src/dst per node ----------------
__global__ void k_node(const float* __restrict__ emb,
                       const float* __restrict__ W,
                       const float* __restrict__ a) {
    __shared__ float sW[192];
    __shared__ float sa[6];
    int t = threadIdx.x;
    if (t < 192) sW[t] = W[t];
    if (t < 6)   sa[t] = a[t];
    __syncthreads();

    int i = blockIdx.x * blockDim.x + t;
    const float4* ev = (const float4*)(emb + (size_t)i * 64);
    float h0 = 0.f, h1 = 0.f, h2 = 0.f;
#pragma unroll
    for (int k4 = 0; k4 < 16; k4++) {
        float4 e = ev[k4];
        int k = k4 * 4;
        h0 += e.x*sW[k*3+0] + e.y*sW[k*3+3] + e.z*sW[k*3+6] + e.w*sW[k*3+9];
        h1 += e.x*sW[k*3+1] + e.y*sW[k*3+4] + e.z*sW[k*3+7] + e.w*sW[k*3+10];
        h2 += e.x*sW[k*3+2] + e.y*sW[k*3+5] + e.z*sW[k*3+8] + e.w*sW[k*3+11];
    }
    float src = h0*sa[0] + h1*sa[1] + h2*sa[2];
    float dst = h0*sa[3] + h1*sa[4] + h2*sa[5];
    g_tabA[i] = make_float4(0.f, 0.f, dst, h0);
    g_tabB[i] = make_float2(h1, h2);
    g_src[i]  = src;
}

// ---------------- K2: dstmax reduction ----------------
__global__ void k_dstmax() {
    __shared__ float sm[1024];
    int t = threadIdx.x;
    float m = -1e30f;
    for (int i = t; i < N_ENT; i += 1024) m = fmaxf(m, g_tabA[i].z);
    sm[t] = m;
    __syncthreads();
    for (int s = 512; s > 0; s >>= 1) {
        if (t < s) sm[t] = fmaxf(sm[t], sm[t+s]);
        __syncthreads();
    }
    if (t == 0) g_dstmax = sm[0];
}

// ---------------- K3: per-node softmax factors ----------------
__global__ void k_consts() {
    int i = blockIdx.x * blockDim.x + threadIdx.x;
    float dm  = g_dstmax;
    float4 tA = g_tabA[i];
    float dst = tA.z;
    tA.x = expf(dst - dm);              // p_j  (<= 1)
    tA.y = expf(0.2f * (dst - dm));     // q_j  (<= 1)
    g_tabA[i] = tA;

    float src = g_src[i];
    float z   = src + dm;
    float lz  = (z > 0.f) ? z : 0.2f * z;          // leakyrelu(src+dstmax)
    float m   = fmaxf(lz, 9e-15f);                 // safe row max
    float u   = expf(z - m);                       // exp(src+dstmax - m)
    float v   = expf(0.2f * z - m);
    float w0  = expf(9e-15f - m);                  // non-edge weight
    g_rowc[i] = make_float4(u, v, w0, -src);       // thr = -src
}

// ---------------- K4: main pass over adj (HBM-bound) ----------------
__global__ void __launch_bounds__(NT, 1) k_main(const int* __restrict__ adj) {
    int t  = threadIdx.x;
    int j0 = t * NJ;

    // register-cached per-column table (loaded ONCE per block)
    float4 tA[NJ];
    float2 tB[NJ];
#pragma unroll
    for (int k = 0; k < NJ; k++) {
        tA[k] = g_tabA[j0 + k];
        tB[k] = g_tabB[j0 + k];
    }

    __shared__ float red[16 * NT];   // 32 KB

    for (int tile = blockIdx.x; tile < NTILES; tile += gridDim.x) {
        int b    = tile >> 10;              // 1024 row-blocks per batch
        int row0 = (tile & 1023) * NR;
        const int4* ap = (const int4*)(adj + ((size_t)b * N_ENT + row0) * N_ENT + j0);

        // issue all adj loads for the tile up front (MLP)
        int4 av[2 * NR];
#pragma unroll
        for (int r = 0; r < NR; r++) {
            av[2*r]   = __ldg(ap + (size_t)r * (N_ENT/4));
            av[2*r+1] = __ldg(ap + (size_t)r * (N_ENT/4) + 1);
        }

#pragma unroll
        for (int r = 0; r < NR; r++) {
            float4 rc = g_rowc[row0 + r];   // u, v, w0, thr (broadcast)
            int va[NJ];
            *(int4*)&va[0] = av[2*r];
            *(int4*)&va[4] = av[2*r+1];
            float a0 = 0.f, a1 = 0.f, a2 = 0.f, a3 = 0.f;
#pragma unroll
            for (int k = 0; k < NJ; k++) {
                float we = (tA[k].z > rc.w) ? (rc.x * tA[k].x) : (rc.y * tA[k].y);
                float c  = (va[k] > 0) ? we : rc.z;
                a0 += c;
                a1 += c * tA[k].w;
                a2 += c * tB[k].x;
                a3 += c * tB[k].y;
            }
            red[(r*4+0)*NT + t] = a0;
            red[(r*4+1)*NT + t] = a1;
            red[(r*4+2)*NT + t] = a2;
            red[(r*4+3)*NT + t] = a3;
        }
        __syncthreads();

        // 16 outputs, one warp each; conflict-free
        int w = t >> 5, lane = t & 31;
        float s = 0.f;
#pragma unroll
        for (int k = 0; k < 16; k++) s += red[w*NT + k*32 + lane];
#pragma unroll
        for (int o = 16; o > 0; o >>= 1) s += __shfl_xor_sync(0xffffffffu, s, o);
        if (lane == 0) {
            int r = w >> 2, comp = w & 3;
            g_acc[(((size_t)b * N_ENT + row0 + r) << 2) + comp] = s;
        }
        __syncthreads();
    }
}

// ---------------- K5: h_prime = num/denom, ELU, build x ----------------
__global__ void k_x() {
    int idx = blockIdx.x * blockDim.x + threadIdx.x;   // 16384
    float4 acc = *(const float4*)&g_acc[(size_t)idx * 4];
    float inv = 1.0f / acc.x;
    float h0 = acc.y * inv, h1 = acc.z * inv, h2 = acc.w * inv;
    h0 = (h0 > 0.f) ? h0 : (expf(h0) - 1.f);
    h1 = (h1 > 0.f) ? h1 : (expf(h1) - 1.f);
    h2 = (h2 > 0.f) ? h2 : (expf(h2) - 1.f);
    int b = idx >> 12, n = idx & 4095;
    float* xp = g_x + (size_t)b * (N_ENT * NHID) + n * NHID;
    xp[0] = h0; xp[1] = h1; xp[2] = h2;
}

// ---------------- K6: out = x @ fc1_w.T + b ----------------
__global__ void k_fc(const float* __restrict__ w,
                     const float* __restrict__ bias,
                     float* __restrict__ out) {
    int o = blockIdx.x;          // 100 outputs
    int t = threadIdx.x;         // 256 threads
    const float* wr = w + (size_t)o * (N_ENT * NHID);
    float acc0 = 0.f, acc1 = 0.f, acc2 = 0.f, acc3 = 0.f;
    const int K = N_ENT * NHID;  // 12288
    for (int k = t; k < K; k += 256) {
        float wv = wr[k];
        acc0 += wv * g_x[k];
        acc1 += wv * g_x[K + k];
        acc2 += wv * g_x[2*K + k];
        acc3 += wv * g_x[3*K + k];
    }
    __shared__ float sr[4][256];
    sr[0][t] = acc0; sr[1][t] = acc1; sr[2][t] = acc2; sr[3][t] = acc3;
    __syncthreads();
    for (int s = 128; s > 0; s >>= 1) {
        if (t < s) {
            sr[0][t] += sr[0][t+s];
            sr[1][t] += sr[1][t+s];
            sr[2][t] += sr[2][t+s];
            sr[3][t] += sr[3][t+s];
        }
        __syncthreads();
    }
    if (t == 0) {
        float bb = bias[o];
        out[0*100 + o] = sr[0][0] + bb;
        out[1*100 + o] = sr[1][0] + bb;
        out[2*100 + o] = sr[2][0] + bb;
        out[3*100 + o] = sr[3][0] + bb;
    }
}

// ---------------- launcher ----------------
extern "C" void kernel_launch(void* const* d_in, const int* in_sizes, int n_in,
                              void* d_out, int out_size) {
    const int*   adj  = (const int*)  d_in[0];
    const float* emb  = (const float*)d_in[1];
    const float* W    = (const float*)d_in[2];
    const float* a    = (const float*)d_in[3];
    const float* fc1w = (const float*)d_in[4];
    const float* fc1b = (const float*)d_in[5];
    float* out = (float*)d_out;

    k_node  <<<N_ENT/256, 256>>>(emb, W, a);
    k_dstmax<<<1, 1024>>>();
    k_consts<<<N_ENT/256, 256>>>();

    int sms = 148;
    int dev = 0;
    if (cudaGetDevice(&dev) == cudaSuccess) {
        int v = 0;
        if (cudaDeviceGetAttribute(&v, cudaDevAttrMultiProcessorCount, dev) == cudaSuccess && v > 0)
            sms = v;
    }
    k_main<<<sms, NT>>>(adj);

    k_x <<<(BATCH*N_ENT)/256, 256>>>();
    k_fc<<<100, 256>>>(fc1w, fc1b, out);
}